// round 2
// baseline (speedup 1.0000x reference)
#include <cuda_runtime.h>
#include <cuda_bf16.h>

// SNN_18433999634702
// spikes = scan_t { v += x_t @ W^T + b ; s = (v>=1) ; v *= (1-s) } ; out = mean_t(s)
// T=64, B=2048, F=784, O=10. Memory-bound: stream 411 MB of x once (~60us floor).
//
// One CTA per batch element b (2048 CTAs, 224 threads).
// Thread p<196 owns float4 chunk p of the F dimension and keeps W[o][4p..4p+3]
// for all O=10 outputs in registers (loaded once). Per timestep: one LDG.128
// of x (prefetch depth 2), 10x (mul.f32x2 + fma.rn.f32x2), warp shuffle
// reduction of the 10 partial dots, small smem cross-warp combine, then
// threads 0..9 run the IF-neuron scan privately in registers.

#define TT 64
#define BB 2048
#define FF 784
#define OO 10
#define F4 196          // FF / 4
#define NTHREADS 224    // 7 warps; threads 0..195 active on FMA
#define NWARPS 7

__device__ __forceinline__ float2 fmul2(const float2 a, const float2 b) {
    float2 d;
    asm("{\n\t"
        ".reg .b64 ra, rb, rd;\n\t"
        "mov.b64 ra, {%2,%3};\n\t"
        "mov.b64 rb, {%4,%5};\n\t"
        "mul.rn.f32x2 rd, ra, rb;\n\t"
        "mov.b64 {%0,%1}, rd;\n\t"
        "}" : "=f"(d.x), "=f"(d.y) : "f"(a.x), "f"(a.y), "f"(b.x), "f"(b.y));
    return d;
}

__device__ __forceinline__ void ffma2(float2 &c, const float2 a, const float2 b) {
    asm("{\n\t"
        ".reg .b64 ra, rb, rc;\n\t"
        "mov.b64 ra, {%2,%3};\n\t"
        "mov.b64 rb, {%4,%5};\n\t"
        "mov.b64 rc, {%0,%1};\n\t"
        "fma.rn.f32x2 rc, ra, rb, rc;\n\t"
        "mov.b64 {%0,%1}, rc;\n\t"
        "}" : "+f"(c.x), "+f"(c.y) : "f"(a.x), "f"(a.y), "f"(b.x), "f"(b.y));
}

__global__ __launch_bounds__(NTHREADS, 2)
void snn_fused_kernel(const float* __restrict__ x,
                      const float* __restrict__ W,
                      const float* __restrict__ bias,
                      float* __restrict__ out)
{
    __shared__ float sm[NWARPS][OO];

    const int tid  = threadIdx.x;
    const int lane = tid & 31;
    const int wid  = tid >> 5;
    const int b    = blockIdx.x;
    const bool active = (tid < F4);

    // W slice in registers: W[o][4*tid .. 4*tid+3] for all o.
    float4 w[OO];
    if (active) {
#pragma unroll
        for (int o = 0; o < OO; ++o)
            w[o] = *(const float4*)(W + o * FF + tid * 4);
    } else {
#pragma unroll
        for (int o = 0; o < OO; ++o)
            w[o] = make_float4(0.f, 0.f, 0.f, 0.f);
    }

    const float bo = (tid < OO) ? bias[tid] : 0.f;

    const size_t strideT = (size_t)BB * FF;
    const float* xb = x + (size_t)b * FF + tid * 4;

    // Prefetch pipeline, depth 2.
    float4 x0 = active ? *(const float4*)(xb)           : make_float4(0,0,0,0);
    float4 x1 = active ? *(const float4*)(xb + strideT) : make_float4(0,0,0,0);

    float v   = 0.f;   // membrane potential (threads 0..9 only meaningful)
    float cnt = 0.f;   // spike count

    for (int t = 0; t < TT; ++t) {
        const float4 xc = x0;
        x0 = x1;
        x1 = (active && (t + 2) < TT)
                 ? *(const float4*)(xb + (size_t)(t + 2) * strideT)
                 : make_float4(0, 0, 0, 0);

        const float2 xlo = make_float2(xc.x, xc.y);
        const float2 xhi = make_float2(xc.z, xc.w);

        float s[OO];
#pragma unroll
        for (int o = 0; o < OO; ++o) {
            float2 a = fmul2(xlo, make_float2(w[o].x, w[o].y));
            ffma2(a, xhi, make_float2(w[o].z, w[o].w));
            s[o] = a.x + a.y;
        }

        // Warp tree-reduce the 10 partial dots.
#pragma unroll
        for (int o = 0; o < OO; ++o) {
#pragma unroll
            for (int off = 16; off; off >>= 1)
                s[o] += __shfl_down_sync(0xffffffffu, s[o], off);
        }
        if (lane == 0) {
#pragma unroll
            for (int o = 0; o < OO; ++o)
                sm[wid][o] = s[o];
        }
        __syncthreads();

        // Threads 0..9: finish the dot, run the IF neuron step.
        if (tid < OO) {
            float c = bo;
#pragma unroll
            for (int wi = 0; wi < NWARPS; ++wi)
                c += sm[wi][tid];
            v += c;
            if (v >= 1.0f) { cnt += 1.0f; v = 0.f; }
        }
        __syncthreads();   // protect sm[] before next timestep overwrites it
    }

    if (tid < OO)
        out[b * OO + tid] = cnt * (1.0f / TT);
}

extern "C" void kernel_launch(void* const* d_in, const int* in_sizes, int n_in,
                              void* d_out, int out_size) {
    const float* x    = (const float*)d_in[0];  // [64, 2048, 784] f32
    const float* W    = (const float*)d_in[1];  // [10, 784] f32
    const float* bias = (const float*)d_in[2];  // [10] f32
    float* out        = (float*)d_out;          // [2048, 10] f32
    (void)in_sizes; (void)n_in; (void)out_size;

    snn_fused_kernel<<<BB, NTHREADS>>>(x, W, bias, out);
}

// round 15
// speedup vs baseline: 1.9531x; 1.9531x over previous
#include <cuda_runtime.h>
#include <cstdint>

// SNN_18433999634702  —  GEMM + scan decomposition.
// Kernel 1: c[t,b,o] = x[t,b,:] . W[o,:]   (thread owns one (t,b) row; no
//           cross-lane reduction; x staged via cp.async 3-buffer pipeline)
// Kernel 2: per-(b,o) IF-neuron scan over t, coalesced reads of c.

#define TT 64
#define BB 2048
#define FF 784
#define OO 10
#define MM (TT * BB)        // 131072 rows
#define KC 16               // K-chunk (floats)
#define NCHUNK (FF / KC)    // 49
#define ROWS 256            // rows per CTA (1 per thread)
#define THREADS 256
#define PITCH 20            // smem row pitch in floats: 80B -> 16B-aligned segs,
                            // (20*j)%32 distinct over any 8 consecutive lanes
#define BUFSZ (ROWS * PITCH)        // 5120 floats per buffer
#define NBUF 3
#define SMEM_FLOATS (NBUF * BUFSZ + OO * FF)   // 15360 + 7840 = 23200
#define SMEM_BYTES (SMEM_FLOATS * 4)           // 92800 B

__device__ float g_c[MM * OO];   // 5.24 MB scratch: c[(t*BB+b)*OO + o]

__device__ __forceinline__ void ffma2(float2 &c, float ax, float ay,
                                      float bx, float by) {
    asm("{\n\t"
        ".reg .b64 ra, rb, rc;\n\t"
        "mov.b64 ra, {%2,%3};\n\t"
        "mov.b64 rb, {%4,%5};\n\t"
        "mov.b64 rc, {%0,%1};\n\t"
        "fma.rn.f32x2 rc, ra, rb, rc;\n\t"
        "mov.b64 {%0,%1}, rc;\n\t"
        "}" : "+f"(c.x), "+f"(c.y) : "f"(ax), "f"(ay), "f"(bx), "f"(by));
}

__device__ __forceinline__ void cp_async16(uint32_t saddr, const void* gaddr) {
    asm volatile("cp.async.cg.shared.global [%0], [%1], 16;\n"
                 :: "r"(saddr), "l"(gaddr));
}
__device__ __forceinline__ void cp_commit() {
    asm volatile("cp.async.commit_group;\n" ::: "memory");
}
template <int N>
__device__ __forceinline__ void cp_wait() {
    asm volatile("cp.async.wait_group %0;\n" :: "n"(N) : "memory");
}

// Prefetch chunk ck of x into buffer bf: 256 rows x 4 x 16B segments
// = 1024 cp.async ops, 4 per thread. Coalesced: consecutive i -> consecutive
// 16B global segments within a row group.
__device__ __forceinline__ void prefetch_chunk(const float* __restrict__ x,
                                               uint32_t xs_base, int R0,
                                               int tid, int ck, int bf) {
    const int kc_ = ck * KC;
#pragma unroll
    for (int j = 0; j < 4; ++j) {
        int i   = tid + j * THREADS;
        int row = i >> 2;
        int seg = i & 3;
        const float* g = x + (size_t)(R0 + row) * FF + kc_ + seg * 4;
        uint32_t saddr = xs_base +
            (uint32_t)((bf * BUFSZ + row * PITCH + seg * 4) * 4);
        cp_async16(saddr, g);
    }
    cp_commit();
}

__global__ __launch_bounds__(THREADS, 2)
void snn_gemm_kernel(const float* __restrict__ x, const float* __restrict__ W)
{
    extern __shared__ float smem[];
    float* xs = smem;                      // [NBUF][ROWS][PITCH]
    float* ws = smem + NBUF * BUFSZ;       // [OO][FF]

    const int tid = threadIdx.x;
    const int R0  = blockIdx.x * ROWS;
    const uint32_t xs_base = (uint32_t)__cvta_generic_to_shared(xs);

    // Stage W into smem (1960 float4, coalesced).
    for (int i = tid; i < OO * FF / 4; i += THREADS)
        ((float4*)ws)[i] = ((const float4*)W)[i];

    float2 acc[OO];
#pragma unroll
    for (int o = 0; o < OO; ++o) acc[o] = make_float2(0.f, 0.f);

    prefetch_chunk(x, xs_base, R0, tid, 0, 0);

    for (int c = 0; c < NCHUNK; ++c) {
        if (c + 1 < NCHUNK) {
            prefetch_chunk(x, xs_base, R0, tid, c + 1, (c + 1) % NBUF);
            cp_wait<1>();          // chunk c resident; c+1 in flight
        } else {
            cp_wait<0>();
        }
        __syncthreads();           // single barrier/chunk: 3 buffers make the
                                   // prefetch target dead for 2 full chunks

        const float* xr = xs + (c % NBUF) * BUFSZ + tid * PITCH;
        float4 xv[4];
#pragma unroll
        for (int p = 0; p < 4; ++p)
            xv[p] = *(const float4*)(xr + p * 4);

        const int kc = c * KC;
#pragma unroll
        for (int o = 0; o < OO; ++o) {
            const float* wrow = ws + o * FF + kc;
#pragma unroll
            for (int p = 0; p < 4; ++p) {
                float4 wv = *(const float4*)(wrow + p * 4);   // broadcast LDS
                ffma2(acc[o], xv[p].x, xv[p].y, wv.x, wv.y);
                ffma2(acc[o], xv[p].z, xv[p].w, wv.z, wv.w);
            }
        }
    }

    // Write 10 outputs for this row (40B, 8B-aligned -> 5 STG.64).
    float s[OO];
#pragma unroll
    for (int o = 0; o < OO; ++o) s[o] = acc[o].x + acc[o].y;
    float* cout = g_c + (size_t)(R0 + tid) * OO;
#pragma unroll
    for (int p = 0; p < 5; ++p)
        ((float2*)cout)[p] = make_float2(s[2 * p], s[2 * p + 1]);
}

// Kernel 2: per-(b,o) IF scan.  n = b*OO + o; c[t*BB*OO + n] coalesced.
__global__ __launch_bounds__(256)
void snn_scan_kernel(const float* __restrict__ bias, float* __restrict__ out)
{
    const int n = blockIdx.x * blockDim.x + threadIdx.x;
    if (n >= BB * OO) return;
    const float bo = bias[n % OO];

    float v = 0.f, cnt = 0.f;
#pragma unroll
    for (int t = 0; t < TT; ++t) {
        float cv = g_c[(size_t)t * (BB * OO) + n];
        v += cv + bo;
        if (v >= 1.0f) { cnt += 1.0f; v = 0.f; }
    }
    out[n] = cnt * (1.0f / TT);
}

extern "C" void kernel_launch(void* const* d_in, const int* in_sizes, int n_in,
                              void* d_out, int out_size) {
    const float* x    = (const float*)d_in[0];  // [64, 2048, 784] f32
    const float* W    = (const float*)d_in[1];  // [10, 784] f32
    const float* bias = (const float*)d_in[2];  // [10] f32
    float* out        = (float*)d_out;          // [2048, 10] f32
    (void)in_sizes; (void)n_in; (void)out_size;

    static bool attr_set = false;
    if (!attr_set) {   // idempotent host-side attribute, not a stream op
        cudaFuncSetAttribute(snn_gemm_kernel,
                             cudaFuncAttributeMaxDynamicSharedMemorySize,
                             SMEM_BYTES);
        attr_set = true;
    }

    snn_gemm_kernel<<<MM / ROWS, THREADS, SMEM_BYTES>>>(x, W);
    snn_scan_kernel<<<(BB * OO + 255) / 256, 256>>>(bias, out);
}